// round 5
// baseline (speedup 1.0000x reference)
#include <cuda_runtime.h>
#include <math_constants.h>

// Problem shape: inputs [B, T, H, C] = [16, 512, 64, 128] fp32, cummax along T.
// Row-major: index(b,t,h,c) = ((b*T + t)*H + h)*C + c.
// For fixed (b,h,c), elements along T are strided by H*C floats.
// One thread owns one (b, h*C + c) column and scans T serially.
// Loads within an 8-step batch are independent of the running max -> MLP=8.

#define B_DIM 16
#define T_DIM 512
#define HC_DIM (64 * 128)       // 8192 contiguous floats per timestep
#define UNROLL 8

__global__ __launch_bounds__(256)
void cummax_time_kernel(const float* __restrict__ in, float* __restrict__ out) {
    const unsigned col = blockIdx.x * blockDim.x + threadIdx.x;  // 0 .. B*HC-1
    if (col >= (unsigned)(B_DIM * HC_DIM)) return;

    const unsigned b     = col / HC_DIM;
    const unsigned inner = col % HC_DIM;

    const size_t base = (size_t)b * T_DIM * HC_DIM + inner;
    const float* __restrict__ p = in + base;
    float* __restrict__       q = out + base;

    float m = -CUDART_INF_F;

    // 64 outer iterations; each batches 8 strided loads (front-issued by ptxas),
    // then the cheap serial max chain, then 8 strided stores.
    for (int tt = 0; tt < T_DIM; tt += UNROLL) {
        float v[UNROLL];
        #pragma unroll
        for (int i = 0; i < UNROLL; ++i) {
            v[i] = __ldcs(p + (size_t)(tt + i) * HC_DIM);   // streaming load, no L2 pollution
        }
        #pragma unroll
        for (int i = 0; i < UNROLL; ++i) {
            m = fmaxf(m, v[i]);
            v[i] = m;
        }
        #pragma unroll
        for (int i = 0; i < UNROLL; ++i) {
            __stcs(q + (size_t)(tt + i) * HC_DIM, v[i]);    // streaming store
        }
    }
}

extern "C" void kernel_launch(void* const* d_in, const int* in_sizes, int n_in,
                              void* d_out, int out_size) {
    const float* in = (const float*)d_in[0];
    float* out = (float*)d_out;

    const int total_cols = B_DIM * HC_DIM;        // 131072
    const int threads = 256;
    const int blocks = (total_cols + threads - 1) / threads;  // 512

    cummax_time_kernel<<<blocks, threads>>>(in, out);
}

// round 6
// speedup vs baseline: 1.0270x; 1.0270x over previous
#include <cuda_runtime.h>
#include <math_constants.h>

// cummax along T for [B, T, H, C] = [16, 512, 64, 128] fp32.
// One thread per (b, h*C+c) column; serial scan over T (stride H*C floats).
//
// R5 changes vs R2 baseline (94.9us, DRAM=68%):
//  - 128-thread blocks -> 1024 blocks -> 6.92 blocks/SM: kills the 512-block
//    wave quantization (3.46/SM -> 15% tail at starved BW).
//  - UNROLL 8 -> 16: ~56 KB/SM of loads in flight to ride out DRAM latency
//    and store-queue interference in the 50/50 R/W mix.
//  - Base-pointer increment per outer iter; all lane offsets are LDG/STG
//    immediates (i*HC*4 < 2^24).

#define B_DIM 16
#define T_DIM 512
#define HC_DIM (64 * 128)       // 8192 floats per timestep, contiguous
#define UNROLL 16

__global__ __launch_bounds__(128)
void cummax_time_kernel(const float* __restrict__ in, float* __restrict__ out) {
    const unsigned col = blockIdx.x * blockDim.x + threadIdx.x;  // 0 .. B*HC-1, exact

    const unsigned b     = col / HC_DIM;
    const unsigned inner = col % HC_DIM;

    const size_t base = (size_t)b * T_DIM * HC_DIM + inner;
    const float* __restrict__ p = in + base;
    float* __restrict__       q = out + base;

    float m = -CUDART_INF_F;

    // 32 outer iterations; 16 independent strided loads are front-batched
    // (addresses are base + constant immediates), then the serial max chain,
    // then 16 streaming stores.
    #pragma unroll 1
    for (int tt = 0; tt < T_DIM; tt += UNROLL) {
        float v[UNROLL];
        #pragma unroll
        for (int i = 0; i < UNROLL; ++i) {
            v[i] = __ldcs(p + (size_t)i * HC_DIM);   // streaming: evict-first
        }
        #pragma unroll
        for (int i = 0; i < UNROLL; ++i) {
            m = fmaxf(m, v[i]);
            v[i] = m;
        }
        #pragma unroll
        for (int i = 0; i < UNROLL; ++i) {
            __stcs(q + (size_t)i * HC_DIM, v[i]);    // streaming store
        }
        p += (size_t)UNROLL * HC_DIM;
        q += (size_t)UNROLL * HC_DIM;
    }
}

extern "C" void kernel_launch(void* const* d_in, const int* in_sizes, int n_in,
                              void* d_out, int out_size) {
    const float* in = (const float*)d_in[0];
    float* out = (float*)d_out;

    const int total_cols = B_DIM * HC_DIM;           // 131072
    const int threads = 128;
    const int blocks = total_cols / threads;         // 1024, exact

    cummax_time_kernel<<<blocks, threads>>>(in, out);
}